// round 4
// baseline (speedup 1.0000x reference)
#include <cuda_runtime.h>
#include <cstddef>

typedef unsigned long long u64;

#define BATCH 512
#define SEQT  1024
#define NG    256

// ---------------- scratch (static device globals: allowed; no runtime alloc) ----
__device__ float g_g1[(size_t)BATCH * SEQT * 512];  // layer1 gate preacts, both dirs (1.07 GB)
__device__ float g_h1[(size_t)BATCH * SEQT * 128];  // layer1 output [fwd|bwd]      (268 MB)
__device__ float g_g2[(size_t)BATCH * SEQT * 256];  // layer2-fwd gate preacts      (536 MB)
__device__ float g_h2[BATCH * 64];                  // layer2-fwd final h

// ---------------- packed fp32x2 helpers (Blackwell FFMA2) -----------------------
static __device__ __forceinline__ u64 pk2(float a, float b) {
    u64 r;
    asm("mov.b64 %0, {%1, %2};" : "=l"(r) : "r"(__float_as_uint(a)), "r"(__float_as_uint(b)));
    return r;
}
static __device__ __forceinline__ float2 upk2(u64 v) {
    unsigned int lo, hi;
    asm("mov.b64 {%0, %1}, %2;" : "=r"(lo), "=r"(hi) : "l"(v));
    return make_float2(__uint_as_float(lo), __uint_as_float(hi));
}
static __device__ __forceinline__ u64 fma2(u64 a, u64 b, u64 c) {
    u64 d;
    asm("fma.rn.f32x2 %0, %1, %2, %3;" : "=l"(d) : "l"(a), "l"(b), "l"(c));
    return d;
}

static __device__ __forceinline__ float sigf(float x) {
    return __fdividef(1.f, 1.f + __expf(-x));
}
static __device__ __forceinline__ float tnhf(float x) {
    return __fdividef(2.f, 1.f + __expf(-2.f * x)) - 1.f;
}

// ---------------- gx GEMM: C[M][N] = A[M][128] * W[N][128]^T + (b1[n]+b2[n]) ----
// BM=128, BN=128, BK=8, 256 threads, per-thread 16x4 outputs as 8 m-pairs (f32x2).
// which==0: A=x,    C=g_g1, W=w_ih(l0 both dirs, 512 rows), N=512
// which==1: A=g_h1, C=g_g2, W=w_ih+65536 (l1 fwd, 256 rows), N=256
__global__ __launch_bounds__(256, 2)
void gemm_k(const float* __restrict__ A_ext, const float* __restrict__ wfull,
            const float* __restrict__ bih, const float* __restrict__ bhh, int which)
{
    const float* A;
    float* C;
    const float* W;
    const float* b1;
    const float* b2;
    int N;
    if (which == 0) { A = A_ext; C = g_g1; W = wfull;         b1 = bih;       b2 = bhh;       N = 512; }
    else            { A = g_h1;  C = g_g2; W = wfull + 65536; b1 = bih + 512; b2 = bhh + 512; N = 256; }

    __shared__ alignas(16) float As[8][128];
    __shared__ alignas(16) float Ws[8][128];

    const int tid   = threadIdx.x;
    const int mBase = blockIdx.x * 128;
    const int nBase = blockIdx.y * 128;
    const int lm = tid >> 1;
    const int lk = (tid & 1) * 4;
    const int tx = tid & 31;   // n block: n0 = tx*4
    const int ty = tid >> 5;   // m block: m0 = ty*16

    u64 acc[8][4];
#pragma unroll
    for (int p = 0; p < 8; p++)
#pragma unroll
        for (int q = 0; q < 4; q++) acc[p][q] = 0ULL;

    for (int kb = 0; kb < 16; kb++) {
        float4 av = *(const float4*)&A[(size_t)(mBase + lm) * 128 + kb * 8 + lk];
        float4 wv = *(const float4*)&W[(size_t)(nBase + lm) * 128 + kb * 8 + lk];
        __syncthreads();
        As[lk + 0][lm] = av.x; As[lk + 1][lm] = av.y; As[lk + 2][lm] = av.z; As[lk + 3][lm] = av.w;
        Ws[lk + 0][lm] = wv.x; Ws[lk + 1][lm] = wv.y; Ws[lk + 2][lm] = wv.z; Ws[lk + 3][lm] = wv.w;
        __syncthreads();
#pragma unroll
        for (int kk = 0; kk < 8; kk++) {
            float4 w4 = *(const float4*)&Ws[kk][tx * 4];
            u64 w20 = pk2(w4.x, w4.x);
            u64 w21 = pk2(w4.y, w4.y);
            u64 w22 = pk2(w4.z, w4.z);
            u64 w23 = pk2(w4.w, w4.w);
#pragma unroll
            for (int p = 0; p < 8; p++) {
                u64 a2 = *(const u64*)&As[kk][ty * 16 + p * 2];
                acc[p][0] = fma2(a2, w20, acc[p][0]);
                acc[p][1] = fma2(a2, w21, acc[p][1]);
                acc[p][2] = fma2(a2, w22, acc[p][2]);
                acc[p][3] = fma2(a2, w23, acc[p][3]);
            }
        }
    }

    const int n0 = nBase + tx * 4;
    float bb0 = b1[n0 + 0] + b2[n0 + 0];
    float bb1 = b1[n0 + 1] + b2[n0 + 1];
    float bb2 = b1[n0 + 2] + b2[n0 + 2];
    float bb3 = b1[n0 + 3] + b2[n0 + 3];
#pragma unroll
    for (int p = 0; p < 8; p++) {
        float2 v0 = upk2(acc[p][0]);
        float2 v1 = upk2(acc[p][1]);
        float2 v2 = upk2(acc[p][2]);
        float2 v3 = upk2(acc[p][3]);
        int row0 = mBase + ty * 16 + p * 2;
        float4 lo = make_float4(v0.x + bb0, v1.x + bb1, v2.x + bb2, v3.x + bb3);
        float4 hi = make_float4(v0.y + bb0, v1.y + bb1, v2.y + bb2, v3.y + bb3);
        *(float4*)&C[(size_t)row0 * N + n0]       = lo;
        *(float4*)&C[(size_t)(row0 + 1) * N + n0] = hi;
    }
}

// ---------------- recurrent layer 1 (both dirs), TB=8 batch rows per CTA --------
#define TB1 8
__global__ __launch_bounds__(256, 1)
void rec1_k(const float* __restrict__ whh)
{
    const int dir = blockIdx.y;
    const int b0  = blockIdx.x * TB1;
    const int tid = threadIdx.x;
    const int g   = tid;

    __shared__ u64   hs2[64 * (TB1 / 2)];     // h row-pairs: float pair {r even, r odd}
    __shared__ float gs[256][TB1 + 1];        // gate preacts, padded for bank-freedom

    float wreg[64];
    {
        const float* wp = whh + ((size_t)dir * 256 + g) * 64;   // layer0
#pragma unroll
        for (int j = 0; j < 64; j += 4) {
            float4 v = *(const float4*)&wp[j];
            wreg[j] = v.x; wreg[j + 1] = v.y; wreg[j + 2] = v.z; wreg[j + 3] = v.w;
        }
    }
    hs2[tid] = 0ULL;   // exactly 256 entries
    float c0 = 0.f, c1 = 0.f;

    const size_t gxoff = (size_t)dir * 256 + g;
    float gxc[TB1];
    {
        int t0 = dir ? (SEQT - 1) : 0;
#pragma unroll
        for (int r = 0; r < TB1; r++)
            gxc[r] = g_g1[((size_t)(b0 + r) * SEQT + t0) * 512 + gxoff];
    }

    for (int tt = 0; tt < SEQT; tt++) {
        const int t   = dir ? (SEQT - 1 - tt) : tt;
        const int ttn = (tt < SEQT - 1) ? (tt + 1) : tt;
        const int tn  = dir ? (SEQT - 1 - ttn) : ttn;

        __syncthreads();   // hs2 from previous step's epilogue is ready

        float gxn[TB1];    // prefetch next step's gx (independent of recurrence)
#pragma unroll
        for (int r = 0; r < TB1; r++)
            gxn[r] = g_g1[((size_t)(b0 + r) * SEQT + tn) * 512 + gxoff];

        u64 acc[TB1 / 2];
#pragma unroll
        for (int p = 0; p < TB1 / 2; p++) acc[p] = pk2(gxc[2 * p], gxc[2 * p + 1]);
#pragma unroll
        for (int j = 0; j < 64; j++) {
            u64 w2 = pk2(wreg[j], wreg[j]);
#pragma unroll
            for (int p = 0; p < TB1 / 2; p++)
                acc[p] = fma2(hs2[j * (TB1 / 2) + p], w2, acc[p]);
        }
#pragma unroll
        for (int p = 0; p < TB1 / 2; p++) {
            float2 v = upk2(acc[p]);
            gs[g][2 * p]     = v.x;
            gs[g][2 * p + 1] = v.y;
        }
        __syncthreads();

        // epilogue: each thread updates 2 (row, j) cells; c kept in registers
        {
            int e = tid, r = e >> 6, j = e & 63;
            float iv = sigf(gs[j][r]);
            float fv = sigf(gs[64 + j][r]);
            float gv = tnhf(gs[128 + j][r]);
            float ov = sigf(gs[192 + j][r]);
            c0 = fv * c0 + iv * gv;
            float h = ov * tnhf(c0);
            ((float*)hs2)[j * TB1 + r] = h;
            g_h1[((size_t)(b0 + r) * SEQT + t) * 128 + dir * 64 + j] = h;
        }
        {
            int e = tid + 256, r = e >> 6, j = e & 63;
            float iv = sigf(gs[j][r]);
            float fv = sigf(gs[64 + j][r]);
            float gv = tnhf(gs[128 + j][r]);
            float ov = sigf(gs[192 + j][r]);
            c1 = fv * c1 + iv * gv;
            float h = ov * tnhf(c1);
            ((float*)hs2)[j * TB1 + r] = h;
            g_h1[((size_t)(b0 + r) * SEQT + t) * 128 + dir * 64 + j] = h;
        }
#pragma unroll
        for (int r = 0; r < TB1; r++) gxc[r] = gxn[r];
    }
}

// ---------------- recurrent layer 2 fwd only (final h matters), TB=4 ------------
#define TB2 4
__global__ __launch_bounds__(256, 1)
void rec2_k(const float* __restrict__ whh)
{
    const int b0  = blockIdx.x * TB2;
    const int tid = threadIdx.x;
    const int g   = tid;

    __shared__ u64   hs2[64 * (TB2 / 2)];
    __shared__ float gs[256][TB2 + 1];

    float wreg[64];
    {
        const float* wp = whh + ((size_t)2 * 256 + g) * 64;   // layer1, dir0
#pragma unroll
        for (int j = 0; j < 64; j += 4) {
            float4 v = *(const float4*)&wp[j];
            wreg[j] = v.x; wreg[j + 1] = v.y; wreg[j + 2] = v.z; wreg[j + 3] = v.w;
        }
    }
    if (tid < 64 * (TB2 / 2)) hs2[tid] = 0ULL;
    float c0 = 0.f;

    float gxc[TB2];
#pragma unroll
    for (int r = 0; r < TB2; r++)
        gxc[r] = g_g2[((size_t)(b0 + r) * SEQT + 0) * 256 + g];

    for (int tt = 0; tt < SEQT; tt++) {
        const int tn = (tt < SEQT - 1) ? (tt + 1) : tt;

        __syncthreads();

        float gxn[TB2];
#pragma unroll
        for (int r = 0; r < TB2; r++)
            gxn[r] = g_g2[((size_t)(b0 + r) * SEQT + tn) * 256 + g];

        u64 acc[TB2 / 2];
#pragma unroll
        for (int p = 0; p < TB2 / 2; p++) acc[p] = pk2(gxc[2 * p], gxc[2 * p + 1]);
#pragma unroll
        for (int j = 0; j < 64; j++) {
            u64 w2 = pk2(wreg[j], wreg[j]);
#pragma unroll
            for (int p = 0; p < TB2 / 2; p++)
                acc[p] = fma2(hs2[j * (TB2 / 2) + p], w2, acc[p]);
        }
#pragma unroll
        for (int p = 0; p < TB2 / 2; p++) {
            float2 v = upk2(acc[p]);
            gs[g][2 * p]     = v.x;
            gs[g][2 * p + 1] = v.y;
        }
        __syncthreads();

        {
            int r = tid >> 6, j = tid & 63;
            float iv = sigf(gs[j][r]);
            float fv = sigf(gs[64 + j][r]);
            float gv = tnhf(gs[128 + j][r]);
            float ov = sigf(gs[192 + j][r]);
            c0 = fv * c0 + iv * gv;
            float h = ov * tnhf(c0);
            ((float*)hs2)[j * TB2 + r] = h;
            if (tt == SEQT - 1) g_h2[(b0 + r) * 64 + j] = h;
        }
#pragma unroll
        for (int r = 0; r < TB2; r++) gxc[r] = gxn[r];
    }
}

// ---------------- final: 1-step layer2-bwd at t=T-1 + FC head -------------------
__global__ void final_k(const float* __restrict__ wih, const float* __restrict__ bih,
                        const float* __restrict__ bhh, const float* __restrict__ fcw,
                        const float* __restrict__ fcb, float* __restrict__ out)
{
    const int b = blockIdx.x;
    const int j = threadIdx.x;   // 64 threads

    __shared__ alignas(16) float xr[128];
    __shared__ float red[64];

    xr[j]      = g_h1[((size_t)b * SEQT + (SEQT - 1)) * 128 + j];
    xr[j + 64] = g_h1[((size_t)b * SEQT + (SEQT - 1)) * 128 + 64 + j];
    __syncthreads();

    // layer1 dir1 weights: offset (1*2+1)*256*128 = 98304; biases at 768+*
    const float* wi = wih + 98304 + (size_t)j * 128;
    const float* wg = wih + 98304 + (size_t)(128 + j) * 128;
    const float* wo = wih + 98304 + (size_t)(192 + j) * 128;
    float ai = bih[768 + j]       + bhh[768 + j];
    float ag = bih[768 + 128 + j] + bhh[768 + 128 + j];
    float ao = bih[768 + 192 + j] + bhh[768 + 192 + j];
#pragma unroll 8
    for (int k = 0; k < 128; k += 4) {
        float4 xv = *(const float4*)&xr[k];
        float4 a  = *(const float4*)&wi[k];
        float4 gq = *(const float4*)&wg[k];
        float4 oq = *(const float4*)&wo[k];
        ai += xv.x * a.x  + xv.y * a.y  + xv.z * a.z  + xv.w * a.w;
        ag += xv.x * gq.x + xv.y * gq.y + xv.z * gq.z + xv.w * gq.w;
        ao += xv.x * oq.x + xv.y * oq.y + xv.z * oq.z + xv.w * oq.w;
    }
    // h0=c0=0: c = i*g, h = o*tanh(c)
    float c  = sigf(ai) * tnhf(ag);
    float hb = sigf(ao) * tnhf(c);

    float part = fcw[j] * g_h2[b * 64 + j] + fcw[64 + j] * hb;
    red[j] = part;
    __syncthreads();
    if (j < 32) {
        float v = red[j] + red[j + 32];
#pragma unroll
        for (int o = 16; o; o >>= 1) v += __shfl_down_sync(0xffffffffu, v, o);
        if (j == 0) out[b] = v + fcb[0];
    }
}

// ---------------- launch --------------------------------------------------------
extern "C" void kernel_launch(void* const* d_in, const int* in_sizes, int n_in,
                              void* d_out, int out_size)
{
    (void)in_sizes; (void)n_in; (void)out_size;
    const float* x    = (const float*)d_in[0];
    const float* w_ih = (const float*)d_in[1];
    const float* w_hh = (const float*)d_in[2];
    const float* b_ih = (const float*)d_in[3];
    const float* b_hh = (const float*)d_in[4];
    const float* fc_w = (const float*)d_in[5];
    const float* fc_b = (const float*)d_in[6];
    float* out = (float*)d_out;

    // 1) layer1 input projection, both dirs fused (N=512)
    gemm_k<<<dim3(4096, 4), 256>>>(x, w_ih, b_ih, b_hh, 0);
    // 2) layer1 recurrence (fwd + bwd), writes g_h1
    rec1_k<<<dim3(64, 2), 256>>>(w_hh);
    // 3) layer2-fwd input projection (N=256)
    gemm_k<<<dim3(4096, 2), 256>>>(x, w_ih, b_ih, b_hh, 1);
    // 4) layer2-fwd recurrence, keeps only final h
    rec2_k<<<dim3(128, 1), 256>>>(w_hh);
    // 5) layer2-bwd single step at t=T-1 + FC head
    final_k<<<dim3(512, 1), 64>>>(w_ih, b_ih, b_hh, fc_w, fc_b, out);
}

// round 7
// speedup vs baseline: 1.2474x; 1.2474x over previous
#include <cuda_runtime.h>
#include <cuda_bf16.h>
#include <cstdint>
#include <cstddef>

typedef unsigned long long u64;

#define BATCH 512
#define SEQT  1024

// ---------------- scratch (static device globals) -------------------------------
__device__ float g_g1[(size_t)BATCH * SEQT * 512];   // layer1 gate preacts (1.07 GB)
__device__ float g_g2[(size_t)BATCH * SEQT * 256];   // layer2-fwd gate preacts (536 MB)
__device__ float g_h1[(size_t)BATCH * SEQT * 128];   // layer1 h [fwd|bwd] fp32 (268 MB)
__device__ float g_h2[BATCH * 64];                   // layer2-fwd final h
__device__ __nv_bfloat16 g_wh[768 * 128];            // w_ih split-bf16 hi: l0d0,l0d1,l1d0
__device__ __nv_bfloat16 g_wl[768 * 128];            // w_ih split-bf16 lo

// ---------------- packed fp32x2 helpers -----------------------------------------
static __device__ __forceinline__ u64 pk2(float a, float b) {
    u64 r;
    asm("mov.b64 %0, {%1, %2};" : "=l"(r) : "r"(__float_as_uint(a)), "r"(__float_as_uint(b)));
    return r;
}
static __device__ __forceinline__ float2 upk2(u64 v) {
    unsigned int lo, hi;
    asm("mov.b64 {%0, %1}, %2;" : "=r"(lo), "=r"(hi) : "l"(v));
    return make_float2(__uint_as_float(lo), __uint_as_float(hi));
}
static __device__ __forceinline__ u64 fma2(u64 a, u64 b, u64 c) {
    u64 d;
    asm("fma.rn.f32x2 %0, %1, %2, %3;" : "=l"(d) : "l"(a), "l"(b), "l"(c));
    return d;
}
static __device__ __forceinline__ float sigf(float x) {
    return __fdividef(1.f, 1.f + __expf(-x));
}
static __device__ __forceinline__ float tnhf(float x) {
    return __fdividef(2.f, 1.f + __expf(-2.f * x)) - 1.f;
}

// ---------------- mma.sync / ldmatrix helpers ------------------------------------
static __device__ __forceinline__ uint32_t smem_u32(const void* p) {
    uint32_t a;
    asm("{ .reg .u64 t; cvta.to.shared.u64 t, %1; cvt.u32.u64 %0, t; }" : "=r"(a) : "l"(p));
    return a;
}
#define LDSM4(d0, d1, d2, d3, a)                                                     \
    asm volatile("ldmatrix.sync.aligned.m8n8.x4.shared.b16 {%0,%1,%2,%3}, [%4];"     \
                 : "=r"(d0), "=r"(d1), "=r"(d2), "=r"(d3) : "r"(a))

static __device__ __forceinline__ void mma16816(float* d, const uint32_t* a,
                                                const uint32_t* b) {
    asm volatile(
        "mma.sync.aligned.m16n8k16.row.col.f32.bf16.bf16.f32 "
        "{%0,%1,%2,%3}, {%4,%5,%6,%7}, {%8,%9}, {%0,%1,%2,%3};"
        : "+f"(d[0]), "+f"(d[1]), "+f"(d[2]), "+f"(d[3])
        : "r"(a[0]), "r"(a[1]), "r"(a[2]), "r"(a[3]), "r"(b[0]), "r"(b[1]));
}

// split one fp32 into bf16 hi + bf16 lo (residual)
static __device__ __forceinline__ void split8(const float* v, uint4& hi, uint4& lo) {
    unsigned hw[4], lw[4];
#pragma unroll
    for (int p = 0; p < 4; p++) {
        __nv_bfloat16 h0 = __float2bfloat16(v[2 * p]);
        __nv_bfloat16 h1 = __float2bfloat16(v[2 * p + 1]);
        float r0 = v[2 * p]     - __bfloat162float(h0);
        float r1 = v[2 * p + 1] - __bfloat162float(h1);
        __nv_bfloat16 l0 = __float2bfloat16(r0);
        __nv_bfloat16 l1 = __float2bfloat16(r1);
        hw[p] = (unsigned)(*(unsigned short*)&h0) | ((unsigned)(*(unsigned short*)&h1) << 16);
        lw[p] = (unsigned)(*(unsigned short*)&l0) | ((unsigned)(*(unsigned short*)&l1) << 16);
    }
    hi = make_uint4(hw[0], hw[1], hw[2], hw[3]);
    lo = make_uint4(lw[0], lw[1], lw[2], lw[3]);
}

// ---------------- weight split conversion (tiny) --------------------------------
__global__ void conv_w_k(const float* __restrict__ w) {
    int i = blockIdx.x * blockDim.x + threadIdx.x;
    if (i < 768 * 128) {
        float v = w[i];
        __nv_bfloat16 h = __float2bfloat16(v);
        g_wh[i] = h;
        g_wl[i] = __float2bfloat16(v - __bfloat162float(h));
    }
}

// ---------------- HMMA split-bf16 GEMM: C = A[M,128] @ W[N,128]^T + b -----------
// CTA: 128-row M tile; A staged once (fp32->split bf16, swizzled); loop N-blocks.
// 8 warps = 4M x 2N; warp tile 32M x 64N; k-step 16 (8 steps).
__global__ __launch_bounds__(256, 1)
void gemm_mma(const float* __restrict__ x, const float* __restrict__ bih,
              const float* __restrict__ bhh, int which)
{
    const float* Asrc = which ? g_h1 : x;
    float*       C    = which ? g_g2 : g_g1;
    const int N    = which ? 256 : 512;
    const int NBLK = which ? 2 : 4;
    const int boff = which ? 512 : 0;
    const int brow = which ? 512 : 0;      // row offset into g_wh/g_wl

    extern __shared__ __align__(1024) char smem[];
    char* sAh = smem;                      // 32KB each, rows of 256B, chunk16 swizzle
    char* sAl = smem + 32768;
    char* sBh = smem + 65536;
    char* sBl = smem + 98304;
    const uint32_t aAh = smem_u32(sAh), aAl = smem_u32(sAl);
    const uint32_t aBh = smem_u32(sBh), aBl = smem_u32(sBl);

    const int tid  = threadIdx.x;
    const int lane = tid & 31;
    const int wid  = tid >> 5;
    const size_t mBase = (size_t)blockIdx.x * 128;

    // ---- stage A (fp32 -> split bf16), swizzled: off(r,c)=r*256+((c^(r&7))<<4)
    {
        const int ck = tid & 15;
        const int r0 = (tid >> 4) * 8;
#pragma unroll
        for (int i = 0; i < 8; i++) {
            int r = r0 + i;
            float vbuf[8];
            const float4* src = (const float4*)(Asrc + (mBase + r) * 128 + ck * 8);
            float4 v0 = src[0], v1 = src[1];
            vbuf[0] = v0.x; vbuf[1] = v0.y; vbuf[2] = v0.z; vbuf[3] = v0.w;
            vbuf[4] = v1.x; vbuf[5] = v1.y; vbuf[6] = v1.z; vbuf[7] = v1.w;
            uint4 hi, lo;
            split8(vbuf, hi, lo);
            int off = r * 256 + ((ck ^ (r & 7)) << 4);
            *(uint4*)(sAh + off) = hi;
            *(uint4*)(sAl + off) = lo;
        }
    }

    const int mW = (wid & 3) * 32;
    const int nW = (wid >> 2) * 64;

    for (int nb = 0; nb < NBLK; nb++) {
        __syncthreads();   // prev iter's ldmatrix done (and A staging on nb=0)
        // ---- stage B block (already split bf16 in g_wh/g_wl)
        {
            const int ck = tid & 15;
            const int r0 = (tid >> 4) * 8;
#pragma unroll
            for (int i = 0; i < 8; i++) {
                int r = r0 + i;
                size_t srow = (size_t)(brow + nb * 128 + r) * 128 + ck * 8;
                uint4 bh = *(const uint4*)(g_wh + srow);
                uint4 bl = *(const uint4*)(g_wl + srow);
                int off = r * 256 + ((ck ^ (r & 7)) << 4);
                *(uint4*)(sBh + off) = bh;
                *(uint4*)(sBl + off) = bl;
            }
        }
        __syncthreads();

        float acc[2][8][4];
#pragma unroll
        for (int mt = 0; mt < 2; mt++)
#pragma unroll
            for (int nt = 0; nt < 8; nt++)
#pragma unroll
                for (int q = 0; q < 4; q++) acc[mt][nt][q] = 0.f;

#pragma unroll
        for (int kk = 0; kk < 8; kk++) {
            const int kc = kk * 2;     // chunk index of k0 (k0/8)

            uint32_t af[2][2][4];
#pragma unroll
            for (int mt = 0; mt < 2; mt++) {
                int row = mW + mt * 16 + (lane & 15);
                int ch  = kc + (lane >> 4);
                uint32_t off = row * 256 + (((unsigned)(ch ^ (row & 7))) << 4);
                LDSM4(af[0][mt][0], af[0][mt][1], af[0][mt][2], af[0][mt][3], aAh + off);
                LDSM4(af[1][mt][0], af[1][mt][1], af[1][mt][2], af[1][mt][3], aAl + off);
            }

            uint32_t bf[2][8][2];
#pragma unroll
            for (int bt = 0; bt < 4; bt++) {
                int row = nW + bt * 16 + (lane & 7) + ((lane >> 4) << 3);
                int ch  = kc + ((lane >> 3) & 1);
                uint32_t off = row * 256 + (((unsigned)(ch ^ (row & 7))) << 4);
                uint32_t r0, r1, r2, r3;
                LDSM4(r0, r1, r2, r3, aBh + off);
                bf[0][2 * bt][0] = r0; bf[0][2 * bt][1] = r1;
                bf[0][2 * bt + 1][0] = r2; bf[0][2 * bt + 1][1] = r3;
                LDSM4(r0, r1, r2, r3, aBl + off);
                bf[1][2 * bt][0] = r0; bf[1][2 * bt][1] = r1;
                bf[1][2 * bt + 1][0] = r2; bf[1][2 * bt + 1][1] = r3;
            }

#pragma unroll
            for (int mt = 0; mt < 2; mt++)
#pragma unroll
                for (int nt = 0; nt < 8; nt++) {
                    mma16816(acc[mt][nt], af[0][mt], bf[0][nt]);   // hh
                    mma16816(acc[mt][nt], af[0][mt], bf[1][nt]);   // hl
                    mma16816(acc[mt][nt], af[1][mt], bf[0][nt]);   // lh
                }
        }

        // ---- epilogue: bias + store
#pragma unroll
        for (int nt = 0; nt < 8; nt++) {
            int col = nb * 128 + nW + nt * 8 + (lane & 3) * 2;
            float b0 = bih[boff + col]     + bhh[boff + col];
            float b1 = bih[boff + col + 1] + bhh[boff + col + 1];
#pragma unroll
            for (int mt = 0; mt < 2; mt++) {
                size_t row = mBase + mW + mt * 16 + (lane >> 2);
                float2 v01 = make_float2(acc[mt][nt][0] + b0, acc[mt][nt][1] + b1);
                float2 v23 = make_float2(acc[mt][nt][2] + b0, acc[mt][nt][3] + b1);
                *(float2*)&C[row * N + col]       = v01;
                *(float2*)&C[(row + 8) * N + col] = v23;
            }
        }
    }
}

// ---------------- recurrent layer 1 (both dirs), TB=4, occupancy 2 --------------
__global__ __launch_bounds__(256, 2)
void rec1_k(const float* __restrict__ whh)
{
    const int dir = blockIdx.y;
    const int b0  = blockIdx.x * 4;
    const int tid = threadIdx.x;
    const int g   = tid;

    __shared__ alignas(16) float hsf[4][64];    // h, [row][j]
    __shared__ float gs[256][5];                // gate preacts [gate][row]

    u64 wp2[32];                                // j-paired w_hh in regs
    {
        const float* wp = whh + ((size_t)dir * 256 + g) * 64;
#pragma unroll
        for (int q = 0; q < 16; q++) {
            float4 v = *(const float4*)&wp[q * 4];
            wp2[2 * q]     = pk2(v.x, v.y);
            wp2[2 * q + 1] = pk2(v.z, v.w);
        }
    }
    ((float*)hsf)[tid] = 0.f;
    float cc = 0.f;

    const size_t gxoff = (size_t)dir * 256 + g;
    float gxc[4];
    {
        int t0 = dir ? (SEQT - 1) : 0;
#pragma unroll
        for (int r = 0; r < 4; r++)
            gxc[r] = g_g1[((size_t)(b0 + r) * SEQT + t0) * 512 + gxoff];
    }

    for (int tt = 0; tt < SEQT; tt++) {
        const int t   = dir ? (SEQT - 1 - tt) : tt;
        const int ttn = (tt < SEQT - 1) ? (tt + 1) : tt;
        const int tn  = dir ? (SEQT - 1 - ttn) : ttn;

        __syncthreads();    // hsf from previous epilogue ready

        float gxn[4];
#pragma unroll
        for (int r = 0; r < 4; r++)
            gxn[r] = g_g1[((size_t)(b0 + r) * SEQT + tn) * 512 + gxoff];

        u64 a0 = pk2(gxc[0], 0.f), a1 = pk2(gxc[1], 0.f);
        u64 a2 = pk2(gxc[2], 0.f), a3 = pk2(gxc[3], 0.f);
#pragma unroll
        for (int q = 0; q < 16; q++) {
            u64 wA = wp2[2 * q], wB = wp2[2 * q + 1];
            ulonglong2 h0 = *(const ulonglong2*)&hsf[0][q * 4];
            ulonglong2 h1 = *(const ulonglong2*)&hsf[1][q * 4];
            ulonglong2 h2 = *(const ulonglong2*)&hsf[2][q * 4];
            ulonglong2 h3 = *(const ulonglong2*)&hsf[3][q * 4];
            a0 = fma2(h0.x, wA, a0); a0 = fma2(h0.y, wB, a0);
            a1 = fma2(h1.x, wA, a1); a1 = fma2(h1.y, wB, a1);
            a2 = fma2(h2.x, wA, a2); a2 = fma2(h2.y, wB, a2);
            a3 = fma2(h3.x, wA, a3); a3 = fma2(h3.y, wB, a3);
        }
        {
            float2 v;
            v = upk2(a0); gs[g][0] = v.x + v.y;
            v = upk2(a1); gs[g][1] = v.x + v.y;
            v = upk2(a2); gs[g][2] = v.x + v.y;
            v = upk2(a3); gs[g][3] = v.x + v.y;
        }
        __syncthreads();

        {
            const int r = tid >> 6, j = tid & 63;
            float iv = sigf(gs[j][r]);
            float fv = sigf(gs[64 + j][r]);
            float gv = tnhf(gs[128 + j][r]);
            float ov = sigf(gs[192 + j][r]);
            cc = fv * cc + iv * gv;
            float h = ov * tnhf(cc);
            hsf[r][j] = h;
            g_h1[((size_t)(b0 + r) * SEQT + t) * 128 + dir * 64 + j] = h;
        }
#pragma unroll
        for (int r = 0; r < 4; r++) gxc[r] = gxn[r];
    }
}

// ---------------- recurrent layer 2 fwd only, TB=4 ------------------------------
__global__ __launch_bounds__(256, 2)
void rec2_k(const float* __restrict__ whh)
{
    const int b0  = blockIdx.x * 4;
    const int tid = threadIdx.x;
    const int g   = tid;

    __shared__ alignas(16) float hsf[4][64];
    __shared__ float gs[256][5];

    u64 wp2[32];
    {
        const float* wp = whh + ((size_t)(2 * 256) + g) * 64;   // layer1 dir0
#pragma unroll
        for (int q = 0; q < 16; q++) {
            float4 v = *(const float4*)&wp[q * 4];
            wp2[2 * q]     = pk2(v.x, v.y);
            wp2[2 * q + 1] = pk2(v.z, v.w);
        }
    }
    ((float*)hsf)[tid] = 0.f;
    float cc = 0.f;

    float gxc[4];
#pragma unroll
    for (int r = 0; r < 4; r++)
        gxc[r] = g_g2[((size_t)(b0 + r) * SEQT) * 256 + g];

    for (int tt = 0; tt < SEQT; tt++) {
        const int tn = (tt < SEQT - 1) ? (tt + 1) : tt;

        __syncthreads();

        float gxn[4];
#pragma unroll
        for (int r = 0; r < 4; r++)
            gxn[r] = g_g2[((size_t)(b0 + r) * SEQT + tn) * 256 + g];

        u64 a0 = pk2(gxc[0], 0.f), a1 = pk2(gxc[1], 0.f);
        u64 a2 = pk2(gxc[2], 0.f), a3 = pk2(gxc[3], 0.f);
#pragma unroll
        for (int q = 0; q < 16; q++) {
            u64 wA = wp2[2 * q], wB = wp2[2 * q + 1];
            ulonglong2 h0 = *(const ulonglong2*)&hsf[0][q * 4];
            ulonglong2 h1 = *(const ulonglong2*)&hsf[1][q * 4];
            ulonglong2 h2 = *(const ulonglong2*)&hsf[2][q * 4];
            ulonglong2 h3 = *(const ulonglong2*)&hsf[3][q * 4];
            a0 = fma2(h0.x, wA, a0); a0 = fma2(h0.y, wB, a0);
            a1 = fma2(h1.x, wA, a1); a1 = fma2(h1.y, wB, a1);
            a2 = fma2(h2.x, wA, a2); a2 = fma2(h2.y, wB, a2);
            a3 = fma2(h3.x, wA, a3); a3 = fma2(h3.y, wB, a3);
        }
        {
            float2 v;
            v = upk2(a0); gs[g][0] = v.x + v.y;
            v = upk2(a1); gs[g][1] = v.x + v.y;
            v = upk2(a2); gs[g][2] = v.x + v.y;
            v = upk2(a3); gs[g][3] = v.x + v.y;
        }
        __syncthreads();

        {
            const int r = tid >> 6, j = tid & 63;
            float iv = sigf(gs[j][r]);
            float fv = sigf(gs[64 + j][r]);
            float gv = tnhf(gs[128 + j][r]);
            float ov = sigf(gs[192 + j][r]);
            cc = fv * cc + iv * gv;
            float h = ov * tnhf(cc);
            hsf[r][j] = h;
            if (tt == SEQT - 1) g_h2[(b0 + r) * 64 + j] = h;
        }
#pragma unroll
        for (int r = 0; r < 4; r++) gxc[r] = gxn[r];
    }
}

// ---------------- final: 1-step layer2-bwd at t=T-1 + FC head -------------------
__global__ void final_k(const float* __restrict__ wih, const float* __restrict__ bih,
                        const float* __restrict__ bhh, const float* __restrict__ fcw,
                        const float* __restrict__ fcb, float* __restrict__ out)
{
    const int b = blockIdx.x;
    const int j = threadIdx.x;   // 64 threads

    __shared__ alignas(16) float xr[128];
    __shared__ float red[64];

    xr[j]      = g_h1[((size_t)b * SEQT + (SEQT - 1)) * 128 + j];
    xr[j + 64] = g_h1[((size_t)b * SEQT + (SEQT - 1)) * 128 + 64 + j];
    __syncthreads();

    const float* wi = wih + 98304 + (size_t)j * 128;
    const float* wg = wih + 98304 + (size_t)(128 + j) * 128;
    const float* wo = wih + 98304 + (size_t)(192 + j) * 128;
    float ai = bih[768 + j]       + bhh[768 + j];
    float ag = bih[768 + 128 + j] + bhh[768 + 128 + j];
    float ao = bih[768 + 192 + j] + bhh[768 + 192 + j];
#pragma unroll 8
    for (int k = 0; k < 128; k += 4) {
        float4 xv = *(const float4*)&xr[k];
        float4 a  = *(const float4*)&wi[k];
        float4 gq = *(const float4*)&wg[k];
        float4 oq = *(const float4*)&wo[k];
        ai += xv.x * a.x  + xv.y * a.y  + xv.z * a.z  + xv.w * a.w;
        ag += xv.x * gq.x + xv.y * gq.y + xv.z * gq.z + xv.w * gq.w;
        ao += xv.x * oq.x + xv.y * oq.y + xv.z * oq.z + xv.w * oq.w;
    }
    float c  = sigf(ai) * tnhf(ag);
    float hb = sigf(ao) * tnhf(c);

    red[j] = fcw[j] * g_h2[b * 64 + j] + fcw[64 + j] * hb;
    __syncthreads();
    if (j < 32) {
        float v = red[j] + red[j + 32];
#pragma unroll
        for (int o = 16; o; o >>= 1) v += __shfl_down_sync(0xffffffffu, v, o);
        if (j == 0) out[b] = v + fcb[0];
    }
}

// ---------------- launch --------------------------------------------------------
extern "C" void kernel_launch(void* const* d_in, const int* in_sizes, int n_in,
                              void* d_out, int out_size)
{
    (void)in_sizes; (void)n_in; (void)out_size;
    const float* x    = (const float*)d_in[0];
    const float* w_ih = (const float*)d_in[1];
    const float* w_hh = (const float*)d_in[2];
    const float* b_ih = (const float*)d_in[3];
    const float* b_hh = (const float*)d_in[4];
    const float* fc_w = (const float*)d_in[5];
    const float* fc_b = (const float*)d_in[6];
    float* out = (float*)d_out;

    const int gemm_smem = 131072;
    cudaFuncSetAttribute(gemm_mma, cudaFuncAttributeMaxDynamicSharedMemorySize, gemm_smem);

    // 0) split-bf16 weight conversion (tiny)
    conv_w_k<<<384, 256>>>(w_ih);
    // 1) layer1 input projection, both dirs (N=512), HMMA split-bf16
    gemm_mma<<<4096, 256, gemm_smem>>>(x, b_ih, b_hh, 0);
    // 2) layer1 recurrence (fwd + bwd), writes fp32 h1
    rec1_k<<<dim3(128, 2), 256>>>(w_hh);
    // 3) layer2-fwd input projection (N=256), HMMA split-bf16
    gemm_mma<<<4096, 256, gemm_smem>>>(x, b_ih, b_hh, 1);
    // 4) layer2-fwd recurrence, keeps only final h
    rec2_k<<<dim3(128, 1), 256>>>(w_hh);
    // 5) layer2-bwd single step at t=T-1 + FC head
    final_k<<<dim3(512, 1), 64>>>(w_ih, b_ih, b_hh, fc_w, fc_b, out);
}